// round 8
// baseline (speedup 1.0000x reference)
#include <cuda_runtime.h>
#include <cuda_bf16.h>
#include <math.h>

#define H 512
#define W 512
#define WPR 16                 // 32-bit words per row
#define GRID 512
#define MISS (1 << 20)

// Scratch (allocation-free rule: __device__ globals)
// Row-packed surface masks: bit b of d_surA[r*16+w] = S at (r, w*32+b).
__device__ unsigned d_surA[H * WPR];   // S  (pred surface)
__device__ unsigned d_surB[H * WPR];   // S' (gt surface)
__device__ float d_rowNum[H];
__device__ float d_rowDen[H];
__device__ unsigned d_cnt;             // zero-init; atomicInc wraps -> reset
__device__ unsigned d_bar;             // grid barrier; reset by final block

// ---------------------------------------------------------------------------
// Nearest set bit in one row within the 3-word window around column c=w*32+bit.
// Exact for dc <= 32 (window fully covers words w-1..w+1). Returns dc or MISS.
// ---------------------------------------------------------------------------
__device__ __forceinline__ int rowwin(const unsigned* __restrict__ rowp,
                                      int w, int bit) {
    unsigned lo  = (w > 0)  ? rowp[w - 1] : 0u;
    unsigned mid = rowp[w];
    unsigned hi  = (w < 15) ? rowp[w + 1] : 0u;
    unsigned long long up =
        (((unsigned long long)(mid & (0xFFFFFFFFu >> (31 - bit)))) << 32) |
        (unsigned long long)lo;
    unsigned long long dn =
        (((unsigned long long)hi) << (32 - bit)) | (unsigned long long)(mid >> bit);
    int dl = up ? (bit + 32) - (63 - __clzll(up)) : MISS;
    int dr = dn ? (__ffsll((long long)dn) - 1)    : MISS;
    return min(dl, dr);
}

// Exact far scan over words beyond w+-1 (window covers those fully). -1 = empty.
__device__ __noinline__ int rowfar(const unsigned* __restrict__ rowp,
                                   int w, int bit) {
    int dl = MISS, dr = MISS;
    for (int ww = w - 2; ww >= 0; --ww) {
        unsigned x = rowp[ww];
        if (x) { dl = (w - ww) * 32 + bit - (31 - __clz(x)); break; }
    }
    for (int ww = w + 2; ww < WPR; ++ww) {
        unsigned x = rowp[ww];
        if (x) { dr = (ww - w) * 32 - bit + (__ffs(x) - 1); break; }
    }
    int d = min(dl, dr);
    return (d >= MISS) ? -1 : d;
}

// Evaluate one row: exact candidate fold into best.
__device__ __forceinline__ void eval_row(const unsigned* __restrict__ rowp,
                                         int dr2, int w, int bit, float& best) {
    int dc = rowwin(rowp, w, bit);
    if (dc <= 32) {
        best = fminf(best, (float)(dr2 + dc * dc));
    } else if ((float)(dr2 + 1024) < best) {
        // window result (33..63) is a valid candidate; far scan may beat it
        int dcf = rowfar(rowp, w, bit);
        int dmin = (dc < MISS) ? ((dcf >= 0) ? min(dc, dcf) : dc) : dcf;
        if (dmin >= 0 && dmin < MISS)
            best = fminf(best, (float)(dr2 + dmin * dmin));
    }
}

// Direct exact 2D nearest-surface-pixel search. sh = staged rows r-8..r+8
// (17 x 16 words); gl = full global mask for the rare |dr| > 8 tail.
__device__ __forceinline__ float search(const unsigned* __restrict__ sh,
                                        const unsigned* __restrict__ gl,
                                        int r, int w, int bit) {
    float best = 1e12f;
    eval_row(sh + 8 * WPR, 0, w, bit, best);
    for (int dr = 1; dr < H; ++dr) {
        int dr2 = dr * dr;
        if ((float)dr2 >= best) break;
        int ru = r - dr, rd = r + dr;
        if (dr <= 8) {
            if (ru >= 0) eval_row(sh + (8 - dr) * WPR, dr2, w, bit, best);
            if (rd <  H) eval_row(sh + (8 + dr) * WPR, dr2, w, bit, best);
        } else {
            if (ru >= 0) eval_row(gl + ru * WPR, dr2, w, bit, best);
            if (rd <  H) eval_row(gl + rd * WPR, dr2, w, bit, best);
        }
    }
    return sqrtf(best);
}

// ---------------------------------------------------------------------------
// Single persistent kernel. Phase 1: block r packs surface row r (row-major
// bit words, erosion done bitwise). Grid barrier. Phase 2: per-pixel exact
// 2D nearest search + masked sums + last-block fold.
// ---------------------------------------------------------------------------
__global__ void __launch_bounds__(512, 4) k_all(const float* __restrict__ pred,
                                                const float* __restrict__ gt,
                                                float* __restrict__ out) {
    __shared__ unsigned cenA[WPR], cenB[WPR];
    __shared__ unsigned sWA[17 * WPR], sWB[17 * WPR];
    __shared__ float wNum[16], wDen[16];
    __shared__ bool  isLast;

    const int r = blockIdx.x;
    const int c = threadIdx.x;
    const int lane = c & 31;
    const int w = c >> 5;            // warp id == word index for this thread

    // ===================== Phase 1: pack row r =====================
    {
        float pu = (r > 0)     ? pred[(r - 1) * W + c] : 0.0f;
        float pc = pred[r * W + c];
        float pd = (r < H - 1) ? pred[(r + 1) * W + c] : 0.0f;
        float gu = (r > 0)     ? gt[(r - 1) * W + c] : 0.0f;
        float gc = gt[r * W + c];
        float gd = (r < H - 1) ? gt[(r + 1) * W + c] : 0.0f;

        unsigned buA = __ballot_sync(0xFFFFFFFFu, pu != 0.0f);
        unsigned bcA = __ballot_sync(0xFFFFFFFFu, pc != 0.0f);
        unsigned bdA = __ballot_sync(0xFFFFFFFFu, pd != 0.0f);
        unsigned buB = __ballot_sync(0xFFFFFFFFu, gu != 0.0f);
        unsigned bcB = __ballot_sync(0xFFFFFFFFu, gc != 0.0f);
        unsigned bdB = __ballot_sync(0xFFFFFFFFu, gd != 0.0f);

        if (lane == 0) { cenA[w] = bcA; cenB[w] = bcB; }
        __syncthreads();

        if (lane == 0) {
            unsigned lA = (w > 0)  ? cenA[w - 1] : 0u;
            unsigned rA = (w < 15) ? cenA[w + 1] : 0u;
            unsigned lB = (w > 0)  ? cenB[w - 1] : 0u;
            unsigned rB = (w < 15) ? cenB[w + 1] : 0u;
            unsigned lmA = (bcA << 1) | (lA >> 31);
            unsigned rmA = (bcA >> 1) | (rA << 31);
            unsigned lmB = (bcB << 1) | (lB >> 31);
            unsigned rmB = (bcB >> 1) | (rB << 31);
            d_surA[r * WPR + w] = bcA & ~(buA & bdA & lmA & rmA);
            d_surB[r * WPR + w] = bcB & ~(buB & bdB & lmB & rmB);
        }
    }

    // ===================== Grid barrier =====================
    __syncthreads();
    if (c == 0) {
        __threadfence();
        unsigned arrived = atomicAdd(&d_bar, 1u) + 1u;
        if (arrived < GRID) {
            while (atomicAdd(&d_bar, 0u) < GRID) { __nanosleep(32); }
        }
        __threadfence();
    }
    __syncthreads();

    // ===================== Phase 2: per-pixel 2D search =====================
    // Stage rows r-8..r+8 of both masks (out-of-range -> 0, gated by bounds).
    if (c < 17 * WPR) {
        int k = c >> 4;
        int ww = c & 15;
        int rr = r - 8 + k;
        bool ok = (rr >= 0) && (rr < H);
        sWA[c] = ok ? d_surA[rr * WPR + ww] : 0u;
        sWB[c] = ok ? d_surB[rr * WPR + ww] : 0u;
    }
    __syncthreads();

    const int bit = c & 31;
    const bool onS  = (sWA[8 * WPR + w] >> bit) & 1u;
    const bool onSp = (sWB[8 * WPR + w] >> bit) & 1u;

    float num = 0.0f;
    float den = 0.0f;
    if (onSp) { num += search(sWA, d_surA, r, w, bit); den += 1.0f; }  // dta on S'
    if (onS)  { num += search(sWB, d_surB, r, w, bit); den += 1.0f; }  // dtb on S

    // warp shuffle reduction (deterministic)
    #pragma unroll
    for (int off = 16; off > 0; off >>= 1) {
        num += __shfl_down_sync(0xFFFFFFFFu, num, off);
        den += __shfl_down_sync(0xFFFFFFFFu, den, off);
    }
    if (lane == 0) { wNum[w] = num; wDen[w] = den; }
    __syncthreads();

    if (w == 0) {
        float n = (lane < 16) ? wNum[lane] : 0.0f;
        float d = (lane < 16) ? wDen[lane] : 0.0f;
        #pragma unroll
        for (int off = 8; off > 0; off >>= 1) {
            n += __shfl_down_sync(0xFFFFFFFFu, n, off);
            d += __shfl_down_sync(0xFFFFFFFFu, d, off);
        }
        if (lane == 0) {
            d_rowNum[r] = n;
            d_rowDen[r] = d;
            __threadfence();
            unsigned old = atomicInc(&d_cnt, H - 1);   // wraps -> self-reset
            isLast = (old == H - 1);
        }
    }
    __syncthreads();

    if (isLast) {
        float n = d_rowNum[c];
        float d = d_rowDen[c];
        #pragma unroll
        for (int off = 16; off > 0; off >>= 1) {
            n += __shfl_down_sync(0xFFFFFFFFu, n, off);
            d += __shfl_down_sync(0xFFFFFFFFu, d, off);
        }
        if (lane == 0) { wNum[w] = n; wDen[w] = d; }
        __syncthreads();
        if (w == 0) {
            float nn = (lane < 16) ? wNum[lane] : 0.0f;
            float dd = (lane < 16) ? wDen[lane] : 0.0f;
            #pragma unroll
            for (int off = 8; off > 0; off >>= 1) {
                nn += __shfl_down_sync(0xFFFFFFFFu, nn, off);
                dd += __shfl_down_sync(0xFFFFFFFFu, dd, off);
            }
            if (lane == 0) {
                out[0] = nn / dd;
                d_bar = 0u;        // safe: all blocks passed barrier before d_cnt wrap
            }
        }
    }
}

extern "C" void kernel_launch(void* const* d_in, const int* in_sizes, int n_in,
                              void* d_out, int out_size) {
    const float* pred = (const float*)d_in[0];
    const float* gt   = (const float*)d_in[1];
    float* out = (float*)d_out;

    k_all<<<GRID, 512>>>(pred, gt, out);
}

// round 9
// speedup vs baseline: 1.3821x; 1.3821x over previous
#include <cuda_runtime.h>
#include <cuda_bf16.h>
#include <math.h>

#define H 512
#define W 512
#define WPR 16                 // 32-bit words per row
#define GRID 512
#define PBLK 128               // phase-2 working blocks (4 rows each)
#define MISS (1 << 20)

// Scratch (allocation-free rule: __device__ globals)
__device__ unsigned d_surA[H * WPR];   // S  (pred surface), row-packed bits
__device__ unsigned d_surB[H * WPR];   // S' (gt surface)
__device__ float d_blkNum[PBLK];
__device__ float d_blkDen[PBLK];
__device__ unsigned d_cnt;             // zero-init; atomicInc wraps -> reset
__device__ unsigned d_bar;             // grid barrier; reset by final block

// ===========================================================================
// Cold-path exact per-pixel search on GLOBAL row-packed mask (from R8, exact).
// Probability of use ~1e-6 for the whole image; correctness insurance only.
// ===========================================================================
__device__ __forceinline__ int rowwin_g(const unsigned* __restrict__ rowp,
                                        int w, int bit) {
    unsigned lo  = (w > 0)  ? rowp[w - 1] : 0u;
    unsigned mid = rowp[w];
    unsigned hi  = (w < 15) ? rowp[w + 1] : 0u;
    unsigned long long up =
        (((unsigned long long)(mid & (0xFFFFFFFFu >> (31 - bit)))) << 32) |
        (unsigned long long)lo;
    unsigned long long dn =
        (((unsigned long long)hi) << (32 - bit)) | (unsigned long long)(mid >> bit);
    int dl = up ? (bit + 32) - (63 - __clzll(up)) : MISS;
    int dr = dn ? (__ffsll((long long)dn) - 1)    : MISS;
    return min(dl, dr);
}

__device__ __noinline__ int rowfar_g(const unsigned* __restrict__ rowp,
                                     int w, int bit) {
    int dl = MISS, dr = MISS;
    for (int ww = w - 2; ww >= 0; --ww) {
        unsigned x = rowp[ww];
        if (x) { dl = (w - ww) * 32 + bit - (31 - __clz(x)); break; }
    }
    for (int ww = w + 2; ww < WPR; ++ww) {
        unsigned x = rowp[ww];
        if (x) { dr = (ww - w) * 32 - bit + (__ffs(x) - 1); break; }
    }
    int d = min(dl, dr);
    return (d >= MISS) ? -1 : d;
}

__device__ __forceinline__ void eval_row_g(const unsigned* __restrict__ rowp,
                                           int dr2, int w, int bit, float& best) {
    int dc = rowwin_g(rowp, w, bit);
    if (dc <= 32) {
        best = fminf(best, (float)(dr2 + dc * dc));
    } else if ((float)(dr2 + 1024) < best) {
        int dcf = rowfar_g(rowp, w, bit);
        int dmin = (dc < MISS) ? ((dcf >= 0) ? min(dc, dcf) : dc) : dcf;
        if (dmin >= 0 && dmin < MISS)
            best = fminf(best, (float)(dr2 + dmin * dmin));
    }
}

__device__ __noinline__ float search_g(const unsigned* __restrict__ gl,
                                       int r, int w, int bit) {
    float best = 1e12f;
    eval_row_g(gl + r * WPR, 0, w, bit, best);
    for (int dr = 1; dr < H; ++dr) {
        int dr2 = dr * dr;
        if ((float)dr2 >= best) break;
        if (r - dr >= 0) eval_row_g(gl + (r - dr) * WPR, dr2, w, bit, best);
        if (r + dr <  H) eval_row_g(gl + (r + dr) * WPR, dr2, w, bit, best);
    }
    return sqrtf(best);
}

// ===========================================================================
// Single persistent kernel.
// Phase 1 (all 512 blocks): block r packs surface row r (bitwise erosion).
// Grid barrier.
// Phase 2 (blocks 0..127): per-word ball-dilation counting, fold.
// ===========================================================================
__global__ void __launch_bounds__(512, 4) k_all(const float* __restrict__ pred,
                                                const float* __restrict__ gt,
                                                float* __restrict__ out) {
    __shared__ unsigned cen[2][WPR];
    __shared__ unsigned stg[2][10][18];   // staged rows (+-3 halo), padded cols
    __shared__ float wNum[16], wDen[16];
    __shared__ bool  isLast;

    const int c = threadIdx.x;
    const int lane = c & 31;
    const int wwarp = c >> 5;

    // ===================== Phase 1: pack row r = blockIdx.x =====================
    {
        const int r = blockIdx.x;
        float pu = (r > 0)     ? pred[(r - 1) * W + c] : 0.0f;
        float pc = pred[r * W + c];
        float pd = (r < H - 1) ? pred[(r + 1) * W + c] : 0.0f;
        float gu = (r > 0)     ? gt[(r - 1) * W + c] : 0.0f;
        float gc = gt[r * W + c];
        float gd = (r < H - 1) ? gt[(r + 1) * W + c] : 0.0f;

        unsigned buA = __ballot_sync(0xFFFFFFFFu, pu != 0.0f);
        unsigned bcA = __ballot_sync(0xFFFFFFFFu, pc != 0.0f);
        unsigned bdA = __ballot_sync(0xFFFFFFFFu, pd != 0.0f);
        unsigned buB = __ballot_sync(0xFFFFFFFFu, gu != 0.0f);
        unsigned bcB = __ballot_sync(0xFFFFFFFFu, gc != 0.0f);
        unsigned bdB = __ballot_sync(0xFFFFFFFFu, gd != 0.0f);

        if (lane == 0) { cen[0][wwarp] = bcA; cen[1][wwarp] = bcB; }
        __syncthreads();

        if (lane == 0) {
            unsigned lA = (wwarp > 0)  ? cen[0][wwarp - 1] : 0u;
            unsigned rA = (wwarp < 15) ? cen[0][wwarp + 1] : 0u;
            unsigned lB = (wwarp > 0)  ? cen[1][wwarp - 1] : 0u;
            unsigned rB = (wwarp < 15) ? cen[1][wwarp + 1] : 0u;
            unsigned lmA = (bcA << 1) | (lA >> 31);
            unsigned rmA = (bcA >> 1) | (rA << 31);
            unsigned lmB = (bcB << 1) | (lB >> 31);
            unsigned rmB = (bcB >> 1) | (rB << 31);
            d_surA[r * WPR + wwarp] = bcA & ~(buA & bdA & lmA & rmA);
            d_surB[r * WPR + wwarp] = bcB & ~(buB & bdB & lmB & rmB);
        }
    }

    // ===================== Grid barrier =====================
    __syncthreads();
    if (c == 0) {
        __threadfence();
        unsigned arrived = atomicAdd(&d_bar, 1u) + 1u;
        if (arrived < GRID) {
            while (atomicAdd(&d_bar, 0u) < GRID) { __nanosleep(32); }
        }
        __threadfence();
    }
    __syncthreads();

    if (blockIdx.x >= PBLK) return;      // only 128 blocks do phase 2

    // ===================== Phase 2: per-word counting =====================
    const int b = blockIdx.x;            // rows b*4 .. b*4+3

    // Stage rows b*4-3 .. b*4+6 of both masks into padded shared (18 wide).
    if (c < 320) {
        int f = c / 160, rest = c % 160;
        int rr = rest >> 4, ww = rest & 15;
        int gr = b * 4 - 3 + rr;
        bool ok = (gr >= 0) && (gr < H);
        const unsigned* src = f ? d_surB : d_surA;
        stg[f][rr][ww + 1] = ok ? src[gr * WPR + ww] : 0u;
    } else if (c < 360) {
        int idx = c - 320;               // 40 pad words -> 0
        int f = idx / 20, rest = idx % 20;
        stg[f][rest >> 1][(rest & 1) ? 17 : 0] = 0u;
    }
    __syncthreads();

    float num = 0.0f;
    float den = 0.0f;

    if (c < 128) {
        const int f = c >> 6;            // dilated (source) feature
        const int local = c & 63;
        const int rloc = local >> 4;     // 0..3
        const int w = local & 15;
        const int gr = b * 4 + rloc;

        // per-|dr| shift aggregates (c_k = feature present at |dc| = k)
        unsigned a0c0, a0c1, a0c2, a0c3;
        unsigned a1c0 = 0, a1c1 = 0, a1c2 = 0, a1c3 = 0;
        unsigned a2c0 = 0, a2c1 = 0, a2c2 = 0;
        unsigned a3c0 = 0, a3c1 = 0;

        #pragma unroll
        for (int dr = -3; dr <= 3; ++dr) {
            const unsigned* row = &stg[f][rloc + 3 + dr][0];
            unsigned lo = row[w], mi = row[w + 1], hi = row[w + 2];
            unsigned c0 = mi;
            unsigned c1 = __funnelshift_r(mi, hi, 1) | __funnelshift_l(lo, mi, 1);
            const int adr = (dr < 0) ? -dr : dr;
            if (adr == 0) {
                a0c0 = c0; a0c1 = c1;
                a0c2 = __funnelshift_r(mi, hi, 2) | __funnelshift_l(lo, mi, 2);
                a0c3 = __funnelshift_r(mi, hi, 3) | __funnelshift_l(lo, mi, 3);
            } else if (adr == 1) {
                a1c0 |= c0; a1c1 |= c1;
                a1c2 |= __funnelshift_r(mi, hi, 2) | __funnelshift_l(lo, mi, 2);
                a1c3 |= __funnelshift_r(mi, hi, 3) | __funnelshift_l(lo, mi, 3);
            } else if (adr == 2) {
                a2c0 |= c0; a2c1 |= c1;
                a2c2 |= __funnelshift_r(mi, hi, 2) | __funnelshift_l(lo, mi, 2);
            } else {
                a3c0 |= c0; a3c1 |= c1;
            }
        }

        const unsigned tgt = stg[f ^ 1][rloc + 3][w + 1];
        den = (float)__popc(tgt);

        // incremental ball dilations: d^2 = 0,1,2,4,5,8,9,10
        unsigned D = a0c0, Dn;
        Dn = D | a0c1 | a1c0; num += 1.0f        * (float)__popc(tgt & Dn & ~D); D = Dn;
        Dn = D | a1c1;        num += 1.41421356f * (float)__popc(tgt & Dn & ~D); D = Dn;
        Dn = D | a0c2 | a2c0; num += 2.0f        * (float)__popc(tgt & Dn & ~D); D = Dn;
        Dn = D | a1c2 | a2c1; num += 2.23606798f * (float)__popc(tgt & Dn & ~D); D = Dn;
        Dn = D | a2c2;        num += 2.82842712f * (float)__popc(tgt & Dn & ~D); D = Dn;
        Dn = D | a0c3 | a3c0; num += 3.0f        * (float)__popc(tgt & Dn & ~D); D = Dn;
        Dn = D | a1c3 | a3c1; num += 3.16227766f * (float)__popc(tgt & Dn & ~D); D = Dn;

        // cold exact fallback for pixels with d^2 > 10 (probability ~1e-6 total)
        unsigned rem = tgt & ~D;
        while (rem) {
            int bt = __ffs(rem) - 1;
            rem &= rem - 1u;
            num += search_g(f ? d_surB : d_surA, gr, w, bt);
        }
    }

    // ===================== deterministic reduction =====================
    #pragma unroll
    for (int off = 16; off > 0; off >>= 1) {
        num += __shfl_down_sync(0xFFFFFFFFu, num, off);
        den += __shfl_down_sync(0xFFFFFFFFu, den, off);
    }
    if (lane == 0) { wNum[wwarp] = num; wDen[wwarp] = den; }
    __syncthreads();

    if (wwarp == 0) {
        float n = (lane < 16) ? wNum[lane] : 0.0f;
        float d = (lane < 16) ? wDen[lane] : 0.0f;
        #pragma unroll
        for (int off = 8; off > 0; off >>= 1) {
            n += __shfl_down_sync(0xFFFFFFFFu, n, off);
            d += __shfl_down_sync(0xFFFFFFFFu, d, off);
        }
        if (lane == 0) {
            d_blkNum[b] = n;
            d_blkDen[b] = d;
            __threadfence();
            unsigned old = atomicInc(&d_cnt, PBLK - 1);  // wraps -> self-reset
            isLast = (old == PBLK - 1);
        }
    }
    __syncthreads();

    if (isLast) {
        float n = (c < PBLK) ? d_blkNum[c] : 0.0f;
        float d = (c < PBLK) ? d_blkDen[c] : 0.0f;
        #pragma unroll
        for (int off = 16; off > 0; off >>= 1) {
            n += __shfl_down_sync(0xFFFFFFFFu, n, off);
            d += __shfl_down_sync(0xFFFFFFFFu, d, off);
        }
        if (lane == 0) { wNum[wwarp] = n; wDen[wwarp] = d; }
        __syncthreads();
        if (wwarp == 0) {
            float nn = (lane < 16) ? wNum[lane] : 0.0f;
            float dd = (lane < 16) ? wDen[lane] : 0.0f;
            #pragma unroll
            for (int off = 8; off > 0; off >>= 1) {
                nn += __shfl_down_sync(0xFFFFFFFFu, nn, off);
                dd += __shfl_down_sync(0xFFFFFFFFu, dd, off);
            }
            if (lane == 0) {
                out[0] = nn / dd;
                d_bar = 0u;    // all 512 blocks already passed the barrier
            }
        }
    }
}

extern "C" void kernel_launch(void* const* d_in, const int* in_sizes, int n_in,
                              void* d_out, int out_size) {
    const float* pred = (const float*)d_in[0];
    const float* gt   = (const float*)d_in[1];
    float* out = (float*)d_out;

    k_all<<<GRID, 512>>>(pred, gt, out);
}